// round 10
// baseline (speedup 1.0000x reference)
#include <cuda_runtime.h>
#include <cstdint>

// ---------------------------------------------------------------------------
// CNN(2x conv/bn/relu/pool) -> 2-layer LSTM over a single 8192-step chain.
// R10: R9 skeleton verbatim (proven, 12.5ms). SINGLE delta: LSTM thread remap
// tid = 16*k + 4*gate + q so all 4 gates of one h-index are intra-warp;
// gate gather via 3 index-shfls; mid-step __syncthreads + gbuf removed.
// ---------------------------------------------------------------------------

#define NSTEPS 8192
#define HDIM   196
#define GDIM   784
#define CL     7
#define KPC    28
#define NTHR   448
#define NW2    14            // GEMM1 worker CTAs (bid 14..27)
#define NGRID  28            // 4 clusters total
#define HPAD   208           // padded h buffer length (floats)
#define QSEG   52            // K-elements per q class (q==3: 40 real + 12 pad)

// device scratch
__device__ float g_feats[NSTEPS * HDIM];
__device__ float g_xw0[NSTEPS * GDIM];
__device__ float g_xw1[NSTEPS * GDIM];
__device__ float g_ys0[NSTEPS * HDIM];
__device__ float g_ys1[NSTEPS * HDIM];
__device__ float g_WT0[HDIM * GDIM];
__device__ float g_WT1[HDIM * GDIM];
__device__ int   g_flag1[NSTEPS / 16];
__device__ int   g_progress0;

__device__ __forceinline__ float fsigm(float x) { return 1.0f / (1.0f + __expf(-x)); }
__device__ __forceinline__ float ftanh(float x) { return 1.0f - 2.0f / (__expf(2.0f * x) + 1.0f); }

__device__ __forceinline__ uint32_t smem_u32(const void* p) {
    uint32_t a;
    asm("{ .reg .u64 t; cvta.to.shared.u64 t, %1; cvt.u32.u64 %0, t; }" : "=r"(a) : "l"(p));
    return a;
}
__device__ __forceinline__ void st_dsmem_f32(uint32_t addr, uint32_t peer, float v) {
    uint32_t r;
    asm volatile("mapa.shared::cluster.u32 %0, %1, %2;" : "=r"(r) : "r"(addr), "r"(peer));
    asm volatile("st.shared::cluster.f32 [%0], %1;" :: "r"(r), "f"(v) : "memory");
}
__device__ __forceinline__ void cluster_sync_() {
    asm volatile("barrier.cluster.arrive.aligned;" ::: "memory");
    asm volatile("barrier.cluster.wait.aligned;" ::: "memory");
}
__device__ __forceinline__ int ld_acq(const int* p) {
    int v;
    asm volatile("ld.acquire.gpu.global.b32 %0, [%1];" : "=r"(v) : "l"(p) : "memory");
    return v;
}
__device__ __forceinline__ void st_rel(int* p, int v) {
    asm volatile("st.release.gpu.global.b32 [%0], %1;" :: "l"(p), "r"(v) : "memory");
}

__global__ void init_kernel() {
    const int i = blockIdx.x * 512 + threadIdx.x;
    if (i < NSTEPS / 16) g_flag1[i] = 0;
    if (i == 0) g_progress0 = 0;
}

// ---------------------------------------------------------------------------
// CNN frontend: one CTA per frame (8192 frames), 196 threads  [proven]
// ---------------------------------------------------------------------------
__global__ void frontend_kernel(
    const float* __restrict__ x,
    const float* __restrict__ w1, const float* __restrict__ b1,
    const float* __restrict__ g1, const float* __restrict__ be1,
    const float* __restrict__ m1, const float* __restrict__ v1,
    const float* __restrict__ w2, const float* __restrict__ b2,
    const float* __restrict__ g2, const float* __restrict__ be2,
    const float* __restrict__ m2, const float* __restrict__ v2)
{
    __shared__ float xin[784];
    __shared__ float a1s[4 * 196];
    __shared__ float w1s[36], w2s[144];
    __shared__ float c1s[4][2], c2s[4][2];

    const int tid = threadIdx.x;   // 196 threads
    const int f = blockIdx.x;      // frame = b*64 + t

    ((float4*)xin)[tid] = ((const float4*)(x + (size_t)f * 784))[tid];
    if (tid < 36) w1s[tid] = w1[tid];
    if (tid >= 36 && tid < 180) w2s[tid - 36] = w2[tid - 36];
    if (tid < 4) {
        float s = g1[tid] * rsqrtf(v1[tid] + 1e-5f);
        c1s[tid][0] = s;
        c1s[tid][1] = be1[tid] + (b1[tid] - m1[tid]) * s;
        float s2 = g2[tid] * rsqrtf(v2[tid] + 1e-5f);
        c2s[tid][0] = s2;
        c2s[tid][1] = be2[tid] + (b2[tid] - m2[tid]) * s2;
    }
    __syncthreads();

    {
        const int pi = tid / 14, pj = tid % 14;
        for (int c = 0; c < 4; ++c) {
            const float* wk = &w1s[c * 9];
            float mx = -1e30f;
            #pragma unroll
            for (int dy2 = 0; dy2 < 2; ++dy2)
            #pragma unroll
            for (int dx2 = 0; dx2 < 2; ++dx2) {
                const int y = 2 * pi + dy2, x0 = 2 * pj + dx2;
                float s = 0.f;
                #pragma unroll
                for (int dy = -1; dy <= 1; ++dy) {
                    const int yy = y + dy;
                    if (yy < 0 || yy >= 28) continue;
                    #pragma unroll
                    for (int dx = -1; dx <= 1; ++dx) {
                        const int xx = x0 + dx;
                        if (xx < 0 || xx >= 28) continue;
                        s = fmaf(xin[yy * 28 + xx], wk[(dy + 1) * 3 + (dx + 1)], s);
                    }
                }
                s = fmaxf(fmaf(s, c1s[c][0], c1s[c][1]), 0.f);
                mx = fmaxf(mx, s);
            }
            a1s[c * 196 + pi * 14 + pj] = mx;
        }
    }
    __syncthreads();

    {
        const int c = tid / 49;
        const int p = tid % 49;
        const int qi = p / 7, qj = p % 7;
        float mx = -1e30f;
        #pragma unroll
        for (int dy2 = 0; dy2 < 2; ++dy2)
        #pragma unroll
        for (int dx2 = 0; dx2 < 2; ++dx2) {
            const int y = 2 * qi + dy2, x0 = 2 * qj + dx2;
            float s = 0.f;
            #pragma unroll
            for (int ic = 0; ic < 4; ++ic) {
                const float* wk = &w2s[(c * 4 + ic) * 9];
                const float* ap = &a1s[ic * 196];
                #pragma unroll
                for (int dy = -1; dy <= 1; ++dy) {
                    const int yy = y + dy;
                    if (yy < 0 || yy >= 14) continue;
                    #pragma unroll
                    for (int dx = -1; dx <= 1; ++dx) {
                        const int xx = x0 + dx;
                        if (xx < 0 || xx >= 14) continue;
                        s = fmaf(ap[yy * 14 + xx], wk[(dy + 1) * 3 + (dx + 1)], s);
                    }
                }
            }
            s = fmaxf(fmaf(s, c2s[c][0], c2s[c][1]), 0.f);
            mx = fmaxf(mx, s);
        }
        const int b = f >> 6, t = f & 63;
        g_feats[(size_t)(t * 128 + b) * HDIM + tid] = mx;
    }
}

// ---------------------------------------------------------------------------
// Transpose Wih (784x196) -> WT (196x784)  [proven]
// ---------------------------------------------------------------------------
__global__ void transpose_kernel(const float* __restrict__ Wih, int sel) {
    float* WT = sel ? g_WT1 : g_WT0;
    const int idx = blockIdx.x * 256 + threadIdx.x;
    if (idx < GDIM * HDIM) {
        const int j = idx / HDIM, k = idx % HDIM;
        WT[k * GDIM + j] = Wih[idx];
    }
}

// ---------------------------------------------------------------------------
// GEMM0: g_xw0 = g_feats @ g_WT0 + (bih0+bhh0)  [proven]
// ---------------------------------------------------------------------------
__global__ __launch_bounds__(224) void gemm0_kernel(
    const float* __restrict__ bih, const float* __restrict__ bhh)
{
    __shared__ float fsh[16 * HDIM];
    const int tid = threadIdx.x;
    const int rb = blockIdx.x * 16;

    for (int i = tid; i < 16 * HDIM; i += 224)
        fsh[i] = g_feats[(size_t)rb * HDIM + i];
    __syncthreads();

    const int j0 = tid, j1 = tid + 224, j2 = tid + 448, j3 = tid + 672;
    const bool has3 = (j3 < GDIM);

    float acc[16][4];
    #pragma unroll
    for (int r = 0; r < 16; ++r)
        #pragma unroll
        for (int q = 0; q < 4; ++q) acc[r][q] = 0.f;

    for (int k = 0; k < HDIM; ++k) {
        const float wv0 = g_WT0[k * GDIM + j0];
        const float wv1 = g_WT0[k * GDIM + j1];
        const float wv2 = g_WT0[k * GDIM + j2];
        const float wv3 = has3 ? g_WT0[k * GDIM + j3] : 0.f;
        #pragma unroll
        for (int r = 0; r < 16; ++r) {
            const float fv = fsh[r * HDIM + k];
            acc[r][0] = fmaf(fv, wv0, acc[r][0]);
            acc[r][1] = fmaf(fv, wv1, acc[r][1]);
            acc[r][2] = fmaf(fv, wv2, acc[r][2]);
            acc[r][3] = fmaf(fv, wv3, acc[r][3]);
        }
    }

    const float bs0 = bih[j0] + bhh[j0];
    const float bs1 = bih[j1] + bhh[j1];
    const float bs2 = bih[j2] + bhh[j2];
    const float bs3 = has3 ? (bih[j3] + bhh[j3]) : 0.f;

    #pragma unroll
    for (int r = 0; r < 16; ++r) {
        const size_t base = (size_t)(rb + r) * GDIM;
        g_xw0[base + j0] = acc[r][0] + bs0;
        g_xw0[base + j1] = acc[r][1] + bs1;
        g_xw0[base + j2] = acc[r][2] + bs2;
        if (has3) g_xw0[base + j3] = acc[r][3] + bs3;
    }
}

// ---------------------------------------------------------------------------
// mega LSTM kernel: 28 CTAs = 4 clusters.
// bid 0-6 layer0 LSTM (no waits), 7-13 layer1 LSTM, 14-27 GEMM1 workers.
// ---------------------------------------------------------------------------
__global__ void __cluster_dims__(CL, 1, 1) __launch_bounds__(NTHR) mega_lstm(
    const float* __restrict__ Whh0, const float* __restrict__ Whh1,
    const float* __restrict__ bih1, const float* __restrict__ bhh1,
    float* __restrict__ out)
{
    __shared__ __align__(16) float SH[3400];
    const int tid = threadIdx.x;
    const int bid = blockIdx.x;

    if (bid < 14) {
        // ---------------- LSTM role ----------------
        const int layer = bid / CL;
        const int rank  = bid % CL;
        const float* Whh = layer ? Whh1 : Whh0;
        const float* xw  = layer ? g_xw1 : g_xw0;
        float* ys        = layer ? g_ys1 : g_ys0;
        float* hfin = out + (layer ? 580 : 384);
        float* cfin = out + (layer ? 972 : 776);

        float* h_sh = SH;              // [2][HPAD], pads zero

        // remap: tid = 16*k + 4*gate + q
        const int q = tid & 3;             // K-quad class
        const int gate = (tid >> 2) & 3;   // 0:i 1:f 2:g 3:o
        const int k = tid >> 4;            // local h index 0..27
        const int R = gate * HDIM + rank * KPC + k;

        // weights: 13 float4 quads covering [q*52, q*52+52); q==3 has 10 real
        // quads ([156,196)) + 3 zero quads (h pads are zero too)
        float4 w[13];
        {
            const float4* wrow = (const float4*)(Whh + (size_t)R * HDIM + q * QSEG);
            const int nreal = (q == 3) ? 10 : 13;
            #pragma unroll
            for (int i = 0; i < 13; ++i)
                w[i] = (i < nreal) ? wrow[i] : make_float4(0.f, 0.f, 0.f, 0.f);
        }

        if (tid < 2 * HPAD) h_sh[tid] = 0.f;   // both buffers incl. pads

        float c = 0.f, hlast = 0.f;
        const int kg = rank * KPC + k;         // global h index (producer owns)
        const bool is_prod = ((tid & 15) == 0);
        const int lbase = (tid & 31) & 16;     // producer lane base in warp
        const uint32_t haddr0 = smem_u32(&h_sh[kg]);
        const uint32_t haddr1 = smem_u32(&h_sh[HPAD + kg]);

        cluster_sync_();

        #pragma unroll 1
        for (int t = 0; t < NSTEPS; ++t) {
            if (layer == 1 && (t & 15) == 0) {   // layer1 gates on xw1 blocks
                if (tid == 0) {
                    const int idx = t >> 4;
                    while (ld_acq(&g_flag1[idx]) == 0) __nanosleep(64);
                }
                __syncthreads();
            }

            const int cur = t & 1;
            float xwv = 0.f;
            if (q == 0) xwv = xw[(size_t)t * GDIM + R];

            // matvec: 13 LDS.128 + 52 scalar FMA per thread
            const float4* hb = (const float4*)(h_sh + cur * HPAD + q * QSEG);
            float a0 = 0.f, a1 = 0.f, a2 = 0.f, a3 = 0.f;
            #pragma unroll
            for (int i = 0; i < 13; ++i) {
                const float4 hv = hb[i];
                a0 = fmaf(hv.x, w[i].x, a0);
                a1 = fmaf(hv.y, w[i].y, a1);
                a2 = fmaf(hv.z, w[i].z, a2);
                a3 = fmaf(hv.w, w[i].w, a3);
            }
            float v = (a0 + a1) + (a2 + a3);
            v += __shfl_xor_sync(0xffffffffu, v, 1);
            v += __shfl_xor_sync(0xffffffffu, v, 2);

            // q==0 lanes: apply gate nonlinearity (gate g's value at lane lbase+4g)
            float gv = 0.f;
            if (q == 0) {
                const float pre = xwv + v;
                gv = (gate == 2) ? ftanh(pre) : fsigm(pre);
            }

            // producers (lane 0/16, gate=0) gather f,g,o from their half-warp
            const float gf = __shfl_sync(0xffffffffu, gv, lbase + 4);
            const float gg = __shfl_sync(0xffffffffu, gv, lbase + 8);
            const float go = __shfl_sync(0xffffffffu, gv, lbase + 12);

            if (is_prod) {
                c = fmaf(gf, c, gv * gg);          // gv = gate i at producer
                const float h = go * ftanh(c);
                hlast = h;
                ys[(size_t)t * HDIM + kg] = h;     // fire-and-forget
                const uint32_t a = (t & 1) ? haddr0 : haddr1;   // next buffer
                #pragma unroll
                for (int p = 0; p < CL; ++p) st_dsmem_f32(a, (uint32_t)p, h);
            }
            cluster_sync_();

            if (layer == 0 && rank == 0 && tid == 0 && (t & 15) == 15)
                st_rel(&g_progress0, t + 1);   // release ys0 rows [0, t]
        }

        if (is_prod) {
            hfin[kg] = hlast;
            cfin[kg] = c;
        }
    } else {
        // ---------------- GEMM1 worker role ----------------
        const int wid = bid - 14;     // 0..13
        float* fsh = SH;              // [16*196]

        for (int bb = wid; bb < NSTEPS / 16; bb += NW2) {
            const int rb = bb * 16;
            if (tid == 0) {
                while (ld_acq(&g_progress0) < rb + 16) __nanosleep(256);
            }
            __syncthreads();

            for (int i = tid; i < 16 * HDIM; i += NTHR)
                fsh[i] = g_ys0[(size_t)rb * HDIM + i];
            __syncthreads();

            const int j0 = tid, j1 = tid + NTHR;
            const bool has1 = (j1 < GDIM);
            float acc[16][2];
            #pragma unroll
            for (int r = 0; r < 16; ++r) { acc[r][0] = 0.f; acc[r][1] = 0.f; }

            for (int k = 0; k < HDIM; ++k) {
                const float wv0 = g_WT1[k * GDIM + j0];
                const float wv1 = has1 ? g_WT1[k * GDIM + j1] : 0.f;
                #pragma unroll
                for (int r = 0; r < 16; ++r) {
                    const float fv = fsh[r * HDIM + k];
                    acc[r][0] = fmaf(fv, wv0, acc[r][0]);
                    acc[r][1] = fmaf(fv, wv1, acc[r][1]);
                }
            }
            const float bs0 = bih1[j0] + bhh1[j0];
            const float bs1 = has1 ? (bih1[j1] + bhh1[j1]) : 0.f;
            #pragma unroll
            for (int r = 0; r < 16; ++r) {
                const size_t base = (size_t)(rb + r) * GDIM;
                g_xw1[base + j0] = acc[r][0] + bs0;
                if (has1) g_xw1[base + j1] = acc[r][1] + bs1;
            }
            __syncthreads();
            if (tid == 0) st_rel(&g_flag1[bb], 1);
        }
    }
}

// ---------------------------------------------------------------------------
// Final logits: ys1 rows [8064,8192) @ Wl.T + bl  -> out[0..384)
// ---------------------------------------------------------------------------
__global__ void final_kernel(const float* __restrict__ Wl,
                             const float* __restrict__ bl,
                             float* __restrict__ out)
{
    const int tid = threadIdx.x;
    const int i = tid / 3, m = tid % 3;
    const float* yr = &g_ys1[(size_t)(NSTEPS - 128 + i) * HDIM];
    const float* wr = &Wl[m * HDIM];
    float acc = 0.f;
    for (int k = 0; k < HDIM; ++k) acc = fmaf(yr[k], wr[k], acc);
    out[i * 3 + m] = acc + bl[m];
}

extern "C" void kernel_launch(void* const* d_in, const int* in_sizes, int n_in,
                              void* d_out, int out_size)
{
    (void)in_sizes; (void)n_in; (void)out_size;
    const float* x    = (const float*)d_in[0];
    const float* w1   = (const float*)d_in[1];
    const float* b1   = (const float*)d_in[2];
    const float* g1   = (const float*)d_in[3];
    const float* be1  = (const float*)d_in[4];
    const float* m1   = (const float*)d_in[5];
    const float* v1   = (const float*)d_in[6];
    const float* w2   = (const float*)d_in[7];
    const float* b2   = (const float*)d_in[8];
    const float* g2   = (const float*)d_in[9];
    const float* be2  = (const float*)d_in[10];
    const float* m2   = (const float*)d_in[11];
    const float* v2   = (const float*)d_in[12];
    const float* Wih0 = (const float*)d_in[13];
    const float* Whh0 = (const float*)d_in[14];
    const float* bih0 = (const float*)d_in[15];
    const float* bhh0 = (const float*)d_in[16];
    const float* Wih1 = (const float*)d_in[17];
    const float* Whh1 = (const float*)d_in[18];
    const float* bih1 = (const float*)d_in[19];
    const float* bhh1 = (const float*)d_in[20];
    const float* Wl   = (const float*)d_in[21];
    const float* bl   = (const float*)d_in[22];
    float* out = (float*)d_out;

    init_kernel<<<2, 512>>>();
    frontend_kernel<<<NSTEPS, 196>>>(x, w1, b1, g1, be1, m1, v1,
                                     w2, b2, g2, be2, m2, v2);
    transpose_kernel<<<(GDIM * HDIM + 255) / 256, 256>>>(Wih0, 0);
    transpose_kernel<<<(GDIM * HDIM + 255) / 256, 256>>>(Wih1, 1);
    gemm0_kernel<<<NSTEPS / 16, 224>>>(bih0, bhh0);
    mega_lstm<<<NGRID, NTHR>>>(Whh0, Whh1, bih1, bhh1, out);
    final_kernel<<<1, 384>>>(Wl, bl, out);
}

// round 11
// speedup vs baseline: 1.2799x; 1.2799x over previous
#include <cuda_runtime.h>
#include <cstdint>

// ---------------------------------------------------------------------------
// CNN(2x conv/bn/relu/pool) -> 2-layer LSTM over a single 8192-step chain.
// R11: R9 base (proven 12.5ms; R10 shfl remap reverted). SINGLE delta:
// cluster barrier split into arrive/wait with xw[t+1] prefetch + layer-1
// flag gate inside the skew window (off the critical path).
// ---------------------------------------------------------------------------

#define NSTEPS 8192
#define HDIM   196
#define GDIM   784
#define CL     7
#define KPC    28
#define NTHR   448
#define NW2    14            // GEMM1 worker CTAs (bid 14..27)
#define NGRID  28            // 4 clusters total
#define HPAD   208           // padded h buffer length (floats)
#define QSEG   52            // K-elements per q class (q==3: 40 real + 12 pad)

// device scratch
__device__ float g_feats[NSTEPS * HDIM];
__device__ float g_xw0[NSTEPS * GDIM];
__device__ float g_xw1[NSTEPS * GDIM];
__device__ float g_ys0[NSTEPS * HDIM];
__device__ float g_ys1[NSTEPS * HDIM];
__device__ float g_WT0[HDIM * GDIM];
__device__ float g_WT1[HDIM * GDIM];
__device__ int   g_flag1[NSTEPS / 16];
__device__ int   g_progress0;

__device__ __forceinline__ float fsigm(float x) { return 1.0f / (1.0f + __expf(-x)); }
__device__ __forceinline__ float ftanh(float x) { return 1.0f - 2.0f / (__expf(2.0f * x) + 1.0f); }

__device__ __forceinline__ uint32_t smem_u32(const void* p) {
    uint32_t a;
    asm("{ .reg .u64 t; cvta.to.shared.u64 t, %1; cvt.u32.u64 %0, t; }" : "=r"(a) : "l"(p));
    return a;
}
__device__ __forceinline__ void st_dsmem_f32(uint32_t addr, uint32_t peer, float v) {
    uint32_t r;
    asm volatile("mapa.shared::cluster.u32 %0, %1, %2;" : "=r"(r) : "r"(addr), "r"(peer));
    asm volatile("st.shared::cluster.f32 [%0], %1;" :: "r"(r), "f"(v) : "memory");
}
__device__ __forceinline__ void cluster_sync_() {
    asm volatile("barrier.cluster.arrive.aligned;" ::: "memory");
    asm volatile("barrier.cluster.wait.aligned;" ::: "memory");
}
__device__ __forceinline__ void cluster_arrive_() {
    asm volatile("barrier.cluster.arrive.aligned;" ::: "memory");
}
__device__ __forceinline__ void cluster_wait_() {
    asm volatile("barrier.cluster.wait.aligned;" ::: "memory");
}
__device__ __forceinline__ int ld_acq(const int* p) {
    int v;
    asm volatile("ld.acquire.gpu.global.b32 %0, [%1];" : "=r"(v) : "l"(p) : "memory");
    return v;
}
__device__ __forceinline__ void st_rel(int* p, int v) {
    asm volatile("st.release.gpu.global.b32 [%0], %1;" :: "l"(p), "r"(v) : "memory");
}

__global__ void init_kernel() {
    const int i = blockIdx.x * 512 + threadIdx.x;
    if (i < NSTEPS / 16) g_flag1[i] = 0;
    if (i == 0) g_progress0 = 0;
}

// ---------------------------------------------------------------------------
// CNN frontend: one CTA per frame (8192 frames), 196 threads  [proven]
// ---------------------------------------------------------------------------
__global__ void frontend_kernel(
    const float* __restrict__ x,
    const float* __restrict__ w1, const float* __restrict__ b1,
    const float* __restrict__ g1, const float* __restrict__ be1,
    const float* __restrict__ m1, const float* __restrict__ v1,
    const float* __restrict__ w2, const float* __restrict__ b2,
    const float* __restrict__ g2, const float* __restrict__ be2,
    const float* __restrict__ m2, const float* __restrict__ v2)
{
    __shared__ float xin[784];
    __shared__ float a1s[4 * 196];
    __shared__ float w1s[36], w2s[144];
    __shared__ float c1s[4][2], c2s[4][2];

    const int tid = threadIdx.x;   // 196 threads
    const int f = blockIdx.x;      // frame = b*64 + t

    ((float4*)xin)[tid] = ((const float4*)(x + (size_t)f * 784))[tid];
    if (tid < 36) w1s[tid] = w1[tid];
    if (tid >= 36 && tid < 180) w2s[tid - 36] = w2[tid - 36];
    if (tid < 4) {
        float s = g1[tid] * rsqrtf(v1[tid] + 1e-5f);
        c1s[tid][0] = s;
        c1s[tid][1] = be1[tid] + (b1[tid] - m1[tid]) * s;
        float s2 = g2[tid] * rsqrtf(v2[tid] + 1e-5f);
        c2s[tid][0] = s2;
        c2s[tid][1] = be2[tid] + (b2[tid] - m2[tid]) * s2;
    }
    __syncthreads();

    {
        const int pi = tid / 14, pj = tid % 14;
        for (int c = 0; c < 4; ++c) {
            const float* wk = &w1s[c * 9];
            float mx = -1e30f;
            #pragma unroll
            for (int dy2 = 0; dy2 < 2; ++dy2)
            #pragma unroll
            for (int dx2 = 0; dx2 < 2; ++dx2) {
                const int y = 2 * pi + dy2, x0 = 2 * pj + dx2;
                float s = 0.f;
                #pragma unroll
                for (int dy = -1; dy <= 1; ++dy) {
                    const int yy = y + dy;
                    if (yy < 0 || yy >= 28) continue;
                    #pragma unroll
                    for (int dx = -1; dx <= 1; ++dx) {
                        const int xx = x0 + dx;
                        if (xx < 0 || xx >= 28) continue;
                        s = fmaf(xin[yy * 28 + xx], wk[(dy + 1) * 3 + (dx + 1)], s);
                    }
                }
                s = fmaxf(fmaf(s, c1s[c][0], c1s[c][1]), 0.f);
                mx = fmaxf(mx, s);
            }
            a1s[c * 196 + pi * 14 + pj] = mx;
        }
    }
    __syncthreads();

    {
        const int c = tid / 49;
        const int p = tid % 49;
        const int qi = p / 7, qj = p % 7;
        float mx = -1e30f;
        #pragma unroll
        for (int dy2 = 0; dy2 < 2; ++dy2)
        #pragma unroll
        for (int dx2 = 0; dx2 < 2; ++dx2) {
            const int y = 2 * qi + dy2, x0 = 2 * qj + dx2;
            float s = 0.f;
            #pragma unroll
            for (int ic = 0; ic < 4; ++ic) {
                const float* wk = &w2s[(c * 4 + ic) * 9];
                const float* ap = &a1s[ic * 196];
                #pragma unroll
                for (int dy = -1; dy <= 1; ++dy) {
                    const int yy = y + dy;
                    if (yy < 0 || yy >= 14) continue;
                    #pragma unroll
                    for (int dx = -1; dx <= 1; ++dx) {
                        const int xx = x0 + dx;
                        if (xx < 0 || xx >= 14) continue;
                        s = fmaf(ap[yy * 14 + xx], wk[(dy + 1) * 3 + (dx + 1)], s);
                    }
                }
            }
            s = fmaxf(fmaf(s, c2s[c][0], c2s[c][1]), 0.f);
            mx = fmaxf(mx, s);
        }
        const int b = f >> 6, t = f & 63;
        g_feats[(size_t)(t * 128 + b) * HDIM + tid] = mx;
    }
}

// ---------------------------------------------------------------------------
// Transpose Wih (784x196) -> WT (196x784)  [proven]
// ---------------------------------------------------------------------------
__global__ void transpose_kernel(const float* __restrict__ Wih, int sel) {
    float* WT = sel ? g_WT1 : g_WT0;
    const int idx = blockIdx.x * 256 + threadIdx.x;
    if (idx < GDIM * HDIM) {
        const int j = idx / HDIM, k = idx % HDIM;
        WT[k * GDIM + j] = Wih[idx];
    }
}

// ---------------------------------------------------------------------------
// GEMM0: g_xw0 = g_feats @ g_WT0 + (bih0+bhh0)  [proven]
// ---------------------------------------------------------------------------
__global__ __launch_bounds__(224) void gemm0_kernel(
    const float* __restrict__ bih, const float* __restrict__ bhh)
{
    __shared__ float fsh[16 * HDIM];
    const int tid = threadIdx.x;
    const int rb = blockIdx.x * 16;

    for (int i = tid; i < 16 * HDIM; i += 224)
        fsh[i] = g_feats[(size_t)rb * HDIM + i];
    __syncthreads();

    const int j0 = tid, j1 = tid + 224, j2 = tid + 448, j3 = tid + 672;
    const bool has3 = (j3 < GDIM);

    float acc[16][4];
    #pragma unroll
    for (int r = 0; r < 16; ++r)
        #pragma unroll
        for (int q = 0; q < 4; ++q) acc[r][q] = 0.f;

    for (int k = 0; k < HDIM; ++k) {
        const float wv0 = g_WT0[k * GDIM + j0];
        const float wv1 = g_WT0[k * GDIM + j1];
        const float wv2 = g_WT0[k * GDIM + j2];
        const float wv3 = has3 ? g_WT0[k * GDIM + j3] : 0.f;
        #pragma unroll
        for (int r = 0; r < 16; ++r) {
            const float fv = fsh[r * HDIM + k];
            acc[r][0] = fmaf(fv, wv0, acc[r][0]);
            acc[r][1] = fmaf(fv, wv1, acc[r][1]);
            acc[r][2] = fmaf(fv, wv2, acc[r][2]);
            acc[r][3] = fmaf(fv, wv3, acc[r][3]);
        }
    }

    const float bs0 = bih[j0] + bhh[j0];
    const float bs1 = bih[j1] + bhh[j1];
    const float bs2 = bih[j2] + bhh[j2];
    const float bs3 = has3 ? (bih[j3] + bhh[j3]) : 0.f;

    #pragma unroll
    for (int r = 0; r < 16; ++r) {
        const size_t base = (size_t)(rb + r) * GDIM;
        g_xw0[base + j0] = acc[r][0] + bs0;
        g_xw0[base + j1] = acc[r][1] + bs1;
        g_xw0[base + j2] = acc[r][2] + bs2;
        if (has3) g_xw0[base + j3] = acc[r][3] + bs3;
    }
}

// ---------------------------------------------------------------------------
// mega LSTM kernel: 28 CTAs = 4 clusters.
// bid 0-6 layer0 LSTM (no waits), 7-13 layer1 LSTM, 14-27 GEMM1 workers.
// ---------------------------------------------------------------------------
__global__ void __cluster_dims__(CL, 1, 1) __launch_bounds__(NTHR) mega_lstm(
    const float* __restrict__ Whh0, const float* __restrict__ Whh1,
    const float* __restrict__ bih1, const float* __restrict__ bhh1,
    float* __restrict__ out)
{
    __shared__ __align__(16) float SH[3400];
    const int tid = threadIdx.x;
    const int bid = blockIdx.x;

    if (bid < 14) {
        // ---------------- LSTM role (R9 mapping) ----------------
        const int layer = bid / CL;
        const int rank  = bid % CL;
        const float* Whh = layer ? Whh1 : Whh0;
        const float* xw  = layer ? g_xw1 : g_xw0;
        float* ys        = layer ? g_ys1 : g_ys0;
        float* hfin = out + (layer ? 580 : 384);
        float* cfin = out + (layer ? 972 : 776);

        float* h_sh = SH;              // [2][HPAD], pads zero
        float* gbuf = SH + 2 * HPAD;   // [112]

        const int o_idx = tid >> 2;
        const int q = tid & 3;
        const int gate = o_idx / KPC;
        const int k_local = o_idx % KPC;
        const int R = gate * HDIM + rank * KPC + k_local;

        // weights: 13 float4 quads covering [q*52, q*52+52); q==3 has 10 real
        // quads ([156,196)) + 3 zero quads (h pads are zero too)
        float4 w[13];
        {
            const float4* wrow = (const float4*)(Whh + (size_t)R * HDIM + q * QSEG);
            const int nreal = (q == 3) ? 10 : 13;
            #pragma unroll
            for (int i = 0; i < 13; ++i)
                w[i] = (i < nreal) ? wrow[i] : make_float4(0.f, 0.f, 0.f, 0.f);
        }

        if (tid < 2 * HPAD) h_sh[tid] = 0.f;   // both buffers incl. pads

        float c = 0.f, hlast = 0.f;
        const int kg = rank * KPC + tid;   // valid tid<28
        uint32_t haddr0 = 0, haddr1 = 0;
        if (tid < KPC) {
            haddr0 = smem_u32(&h_sh[kg]);
            haddr1 = smem_u32(&h_sh[HPAD + kg]);
        }

        cluster_sync_();

        // pre-loop: layer1 gates on first xw1 block; load xw[0]
        if (layer == 1) {
            if (tid == 0) {
                while (ld_acq(&g_flag1[0]) == 0) __nanosleep(64);
            }
            __syncthreads();
        }
        float xwv = 0.f;
        if (q == 0) xwv = xw[R];

        #pragma unroll 1
        for (int t = 0; t < NSTEPS; ++t) {
            const int cur = t & 1;

            // matvec: 13 LDS.128 + 52 scalar FMA per thread
            const float4* hb = (const float4*)(h_sh + cur * HPAD + q * QSEG);
            float a0 = 0.f, a1 = 0.f, a2 = 0.f, a3 = 0.f;
            #pragma unroll
            for (int i = 0; i < 13; ++i) {
                const float4 hv = hb[i];
                a0 = fmaf(hv.x, w[i].x, a0);
                a1 = fmaf(hv.y, w[i].y, a1);
                a2 = fmaf(hv.z, w[i].z, a2);
                a3 = fmaf(hv.w, w[i].w, a3);
            }
            float v = (a0 + a1) + (a2 + a3);
            v += __shfl_xor_sync(0xffffffffu, v, 1);
            v += __shfl_xor_sync(0xffffffffu, v, 2);

            if (q == 0) {
                const float pre = xwv + v;
                gbuf[o_idx] = (gate == 2) ? ftanh(pre) : fsigm(pre);
            }
            __syncthreads();

            if (tid < KPC) {
                const float gi = gbuf[tid];
                const float gf = gbuf[KPC + tid];
                const float gg = gbuf[2 * KPC + tid];
                const float go = gbuf[3 * KPC + tid];
                c = fmaf(gf, c, gi * gg);
                const float h = go * ftanh(c);
                hlast = h;
                ys[(size_t)t * HDIM + kg] = h;
                const uint32_t a = (t & 1) ? haddr0 : haddr1;   // next buffer
                #pragma unroll
                for (int p = 0; p < CL; ++p) st_dsmem_f32(a, (uint32_t)p, h);
            }

            // ---- barrier skew window: arrive, gate+prefetch next xw, wait ----
            cluster_arrive_();
            if (t + 1 < NSTEPS) {
                if (layer == 1 && ((t + 1) & 15) == 0) {
                    if (tid == 0) {
                        const int idx = (t + 1) >> 4;
                        while (ld_acq(&g_flag1[idx]) == 0) __nanosleep(64);
                    }
                    __syncthreads();
                }
                if (q == 0) xwv = xw[(size_t)(t + 1) * GDIM + R];
            }
            cluster_wait_();

            if (layer == 0 && rank == 0 && tid == 0 && (t & 15) == 15)
                st_rel(&g_progress0, t + 1);   // release ys0 rows [0, t]
        }

        if (tid < KPC) {
            hfin[kg] = hlast;
            cfin[kg] = c;
        }
    } else {
        // ---------------- GEMM1 worker role ----------------
        const int wid = bid - 14;     // 0..13
        float* fsh = SH;              // [16*196]

        for (int bb = wid; bb < NSTEPS / 16; bb += NW2) {
            const int rb = bb * 16;
            if (tid == 0) {
                while (ld_acq(&g_progress0) < rb + 16) __nanosleep(256);
            }
            __syncthreads();

            for (int i = tid; i < 16 * HDIM; i += NTHR)
                fsh[i] = g_ys0[(size_t)rb * HDIM + i];
            __syncthreads();

            const int j0 = tid, j1 = tid + NTHR;
            const bool has1 = (j1 < GDIM);
            float acc[16][2];
            #pragma unroll
            for (int r = 0; r < 16; ++r) { acc[r][0] = 0.f; acc[r][1] = 0.f; }

            for (int k = 0; k < HDIM; ++k) {
                const float wv0 = g_WT1[k * GDIM + j0];
                const float wv1 = has1 ? g_WT1[k * GDIM + j1] : 0.f;
                #pragma unroll
                for (int r = 0; r < 16; ++r) {
                    const float fv = fsh[r * HDIM + k];
                    acc[r][0] = fmaf(fv, wv0, acc[r][0]);
                    acc[r][1] = fmaf(fv, wv1, acc[r][1]);
                }
            }
            const float bs0 = bih1[j0] + bhh1[j0];
            const float bs1 = has1 ? (bih1[j1] + bhh1[j1]) : 0.f;
            #pragma unroll
            for (int r = 0; r < 16; ++r) {
                const size_t base = (size_t)(rb + r) * GDIM;
                g_xw1[base + j0] = acc[r][0] + bs0;
                if (has1) g_xw1[base + j1] = acc[r][1] + bs1;
            }
            __syncthreads();
            if (tid == 0) st_rel(&g_flag1[bb], 1);
        }
    }
}

// ---------------------------------------------------------------------------
// Final logits: ys1 rows [8064,8192) @ Wl.T + bl  -> out[0..384)
// ---------------------------------------------------------------------------
__global__ void final_kernel(const float* __restrict__ Wl,
                             const float* __restrict__ bl,
                             float* __restrict__ out)
{
    const int tid = threadIdx.x;
    const int i = tid / 3, m = tid % 3;
    const float* yr = &g_ys1[(size_t)(NSTEPS - 128 + i) * HDIM];
    const float* wr = &Wl[m * HDIM];
    float acc = 0.f;
    for (int k = 0; k < HDIM; ++k) acc = fmaf(yr[k], wr[k], acc);
    out[i * 3 + m] = acc + bl[m];
}

extern "C" void kernel_launch(void* const* d_in, const int* in_sizes, int n_in,
                              void* d_out, int out_size)
{
    (void)in_sizes; (void)n_in; (void)out_size;
    const float* x    = (const float*)d_in[0];
    const float* w1   = (const float*)d_in[1];
    const float* b1   = (const float*)d_in[2];
    const float* g1   = (const float*)d_in[3];
    const float* be1  = (const float*)d_in[4];
    const float* m1   = (const float*)d_in[5];
    const float* v1   = (const float*)d_in[6];
    const float* w2   = (const float*)d_in[7];
    const float* b2   = (const float*)d_in[8];
    const float* g2   = (const float*)d_in[9];
    const float* be2  = (const float*)d_in[10];
    const float* m2   = (const float*)d_in[11];
    const float* v2   = (const float*)d_in[12];
    const float* Wih0 = (const float*)d_in[13];
    const float* Whh0 = (const float*)d_in[14];
    const float* bih0 = (const float*)d_in[15];
    const float* bhh0 = (const float*)d_in[16];
    const float* Wih1 = (const float*)d_in[17];
    const float* Whh1 = (const float*)d_in[18];
    const float* bih1 = (const float*)d_in[19];
    const float* bhh1 = (const float*)d_in[20];
    const float* Wl   = (const float*)d_in[21];
    const float* bl   = (const float*)d_in[22];
    float* out = (float*)d_out;

    init_kernel<<<2, 512>>>();
    frontend_kernel<<<NSTEPS, 196>>>(x, w1, b1, g1, be1, m1, v1,
                                     w2, b2, g2, be2, m2, v2);
    transpose_kernel<<<(GDIM * HDIM + 255) / 256, 256>>>(Wih0, 0);
    transpose_kernel<<<(GDIM * HDIM + 255) / 256, 256>>>(Wih1, 1);
    gemm0_kernel<<<NSTEPS / 16, 224>>>(bih0, bhh0);
    mega_lstm<<<NGRID, NTHR>>>(Whh0, Whh1, bih1, bhh1, out);
    final_kernel<<<1, 384>>>(Wl, bl, out);
}